// round 2
// baseline (speedup 1.0000x reference)
#include <cuda_runtime.h>
#include <math.h>

#define Bdim 8
#define Cdim 32
#define Hdim 128
#define Wdim 128
#define OUTdim 32
#define HW (Hdim*Wdim)            /* 16384 */
#define NPIX (Bdim*HW)            /* 131072 */
#define NBLK_A 128

// ---- scratch (static device globals; no runtime allocation) ----
__device__ float g_conv[4*NPIX];      // raw conv+bias outputs: v0,v1,z0,z1 planes
__device__ float g_partial[NBLK_A*8]; // per-block partial sums (4 sums + 4 sumsq)
__device__ float g_stats[12];         // mean[4], scale[4]=gamma*rsqrt(var+eps), shift[4]=beta

// ---- packed fp32x2 helpers (sm_103a FFMA2; PTX-only, ptxas never auto-fuses) ----
__device__ __forceinline__ void ffma2(unsigned long long &acc,
                                      unsigned long long w,
                                      unsigned long long d) {
    asm("fma.rn.f32x2 %0, %1, %2, %0;" : "+l"(acc) : "l"(w), "l"(d));
}
__device__ __forceinline__ unsigned long long pk2(float lo, float hi) {
    unsigned long long r;
    asm("mov.b64 %0, {%1, %2};" : "=l"(r) : "f"(lo), "f"(hi));
    return r;
}
__device__ __forceinline__ void unpk2(unsigned long long v, float &lo, float &hi) {
    asm("mov.b64 {%0, %1}, %2;" : "=f"(lo), "=f"(hi) : "l"(v));
}

// =====================================================================
// Kernel A: 7-tap vert/horz convs (zero pad) + bias; 4 pixels/thread
// block = 8 rows x 128 cols of one batch image; 256 threads x 4 pixels
// =====================================================================
__global__ __launch_bounds__(256) void convbn_kernel(
    const float* __restrict__ x,
    const float* __restrict__ w_vrt, const float* __restrict__ b_vrt,
    const float* __restrict__ w_hrz, const float* __restrict__ b_hrz)
{
    __shared__ float swv[448], swh[448];   // [2][32][7]
    __shared__ float red[8][8];
    int tid = threadIdx.x;
    for (int i = tid; i < 448; i += 256) { swv[i] = w_vrt[i]; swh[i] = w_hrz[i]; }
    __syncthreads();

    int b  = blockIdx.x >> 4;
    int rg = blockIdx.x & 15;
    int h  = rg*8 + (tid >> 5);
    int w0 = (tid & 31) * 4;
    const float* Xb = x + (size_t)b*Cdim*HW;

    float v0[4]={0,0,0,0}, v1[4]={0,0,0,0}, z0[4]={0,0,0,0}, z1[4]={0,0,0,0};

    for (int c = 0; c < Cdim; ++c) {
        const float* Xc  = Xb + c*HW;
        const float* row = Xc + h*Wdim;

        // vertical: 7 bounds-checked float4 row loads
        #pragma unroll
        for (int t = 0; t < 7; ++t) {
            int hh = h + t - 3;
            float4 xv;
            if (hh >= 0 && hh < Hdim) xv = *(const float4*)(Xc + hh*Wdim + w0);
            else                      xv = make_float4(0.f,0.f,0.f,0.f);
            float wa = swv[c*7+t], wb = swv[224 + c*7+t];
            v0[0]=fmaf(xv.x,wa,v0[0]); v0[1]=fmaf(xv.y,wa,v0[1]);
            v0[2]=fmaf(xv.z,wa,v0[2]); v0[3]=fmaf(xv.w,wa,v0[3]);
            v1[0]=fmaf(xv.x,wb,v1[0]); v1[1]=fmaf(xv.y,wb,v1[1]);
            v1[2]=fmaf(xv.z,wb,v1[2]); v1[3]=fmaf(xv.w,wb,v1[3]);
        }

        // horizontal: window w0-4 .. w0+7 as 3 float4 (zero-filled at edges)
        float xr[12];
        {
            float4 L = (w0 >= 4)   ? *(const float4*)(row + w0 - 4) : make_float4(0.f,0.f,0.f,0.f);
            float4 M = *(const float4*)(row + w0);
            float4 R = (w0 <= 120) ? *(const float4*)(row + w0 + 4) : make_float4(0.f,0.f,0.f,0.f);
            xr[0]=L.x; xr[1]=L.y; xr[2]=L.z;  xr[3]=L.w;
            xr[4]=M.x; xr[5]=M.y; xr[6]=M.z;  xr[7]=M.w;
            xr[8]=R.x; xr[9]=R.y; xr[10]=R.z; xr[11]=R.w;
        }
        #pragma unroll
        for (int t = 0; t < 7; ++t) {
            float wa = swh[c*7+t], wb = swh[224 + c*7+t];
            #pragma unroll
            for (int j = 0; j < 4; ++j) {
                float xv = xr[j + t + 1];           // w0 + j + t - 3
                z0[j] = fmaf(xv, wa, z0[j]);
                z1[j] = fmaf(xv, wb, z1[j]);
            }
        }
    }

    float bv0 = b_vrt[0], bv1 = b_vrt[1], bh0 = b_hrz[0], bh1 = b_hrz[1];
    #pragma unroll
    for (int j = 0; j < 4; ++j) { v0[j]+=bv0; v1[j]+=bv1; z0[j]+=bh0; z1[j]+=bh1; }

    int pixbase = b*HW + h*Wdim + w0;
    *(float4*)&g_conv[          pixbase] = make_float4(v0[0],v0[1],v0[2],v0[3]);
    *(float4*)&g_conv[  NPIX +  pixbase] = make_float4(v1[0],v1[1],v1[2],v1[3]);
    *(float4*)&g_conv[2*NPIX +  pixbase] = make_float4(z0[0],z0[1],z0[2],z0[3]);
    *(float4*)&g_conv[3*NPIX +  pixbase] = make_float4(z1[0],z1[1],z1[2],z1[3]);

    float vals[8];
    vals[0]=v0[0]+v0[1]+v0[2]+v0[3];
    vals[1]=v1[0]+v1[1]+v1[2]+v1[3];
    vals[2]=z0[0]+z0[1]+z0[2]+z0[3];
    vals[3]=z1[0]+z1[1]+z1[2]+z1[3];
    vals[4]=v0[0]*v0[0]+v0[1]*v0[1]+v0[2]*v0[2]+v0[3]*v0[3];
    vals[5]=v1[0]*v1[0]+v1[1]*v1[1]+v1[2]*v1[2]+v1[3]*v1[3];
    vals[6]=z0[0]*z0[0]+z0[1]*z0[1]+z0[2]*z0[2]+z0[3]*z0[3];
    vals[7]=z1[0]*z1[0]+z1[1]*z1[1]+z1[2]*z1[2]+z1[3]*z1[3];

    #pragma unroll
    for (int k = 0; k < 8; ++k) {
        float s = vals[k];
        #pragma unroll
        for (int off = 16; off; off >>= 1) s += __shfl_down_sync(0xffffffffu, s, off);
        if ((tid & 31) == 0) red[tid>>5][k] = s;
    }
    __syncthreads();
    if (tid < 8) {
        float s = 0.f;
        #pragma unroll
        for (int wr = 0; wr < 8; ++wr) s += red[wr][tid];
        g_partial[blockIdx.x*8 + tid] = s;
    }
}

// =====================================================================
// Kernel B: finalize BN stats (deterministic)
// =====================================================================
__global__ void stats_kernel(
    const float* __restrict__ g_vrt, const float* __restrict__ be_vrt,
    const float* __restrict__ g_hrz, const float* __restrict__ be_hrz)
{
    __shared__ float sh[8];
    int k = threadIdx.x;
    if (k < 8) {
        float s = 0.f;
        #pragma unroll 8
        for (int i = 0; i < NBLK_A; ++i) s += g_partial[i*8 + k];
        sh[k] = s;
    }
    __syncwarp();
    if (k < 4) {
        const float inv = 1.f / (float)NPIX;
        float mean = sh[k] * inv;
        float var  = sh[k+4] * inv - mean*mean;
        float gamma = (k < 2) ? g_vrt[k] : g_hrz[k-2];
        float beta  = (k < 2) ? be_vrt[k] : be_hrz[k-2];
        g_stats[k]     = mean;
        g_stats[4 + k] = gamma * rsqrtf(var + 1e-5f);
        g_stats[8 + k] = beta;
    }
}

// =====================================================================
// Kernel C: per-pixel deformable sampling + 32x512 matvec (f32x2 packed)
// =====================================================================
__global__ __launch_bounds__(256, 2) void main_kernel(
    const float* __restrict__ x, const float* __restrict__ w_pk,
    const float* __restrict__ b_pk, float* __restrict__ out)
{
    extern __shared__ float sw[];          // w_pk [32][32][16] = 16384 floats, + bias 32
    float* sb = sw + 16384;
    int tid = threadIdx.x;
    {
        const float4* src = (const float4*)w_pk;
        float4* dst = (float4*)sw;
        #pragma unroll
        for (int i = 0; i < 16; ++i) dst[tid + i*256] = src[tid + i*256];
        if (tid < 32) sb[tid] = b_pk[tid];
    }
    __syncthreads();

    int pix = blockIdx.x*256 + tid;
    int b = pix >> 14; int rem = pix & (HW-1); int h = rem >> 7; int w = rem & 127;

    // gb0..gb3 = 2*sigmoid(BN(conv))
    float gb[4];
    #pragma unroll
    for (int j = 0; j < 4; ++j) {
        float cv = g_conv[j*NPIX + pix];
        float t = (cv - g_stats[j]) * g_stats[4+j] + g_stats[8+j];
        gb[j] = 2.f / (1.f + expf(-t));
    }

    int rm[5], cm[5];
    #pragma unroll
    for (int i = 0; i < 5; ++i) {
        rm[i] = min(max(h + i - 2, 0), 127);
        cm[i] = min(max(w + i - 2, 0), 127);
    }

    int off[16];
    float a[4];
    float eBw, eLw; int eBoff, eLoff;
    {
        float u, q, qlc, qrc, uc;
        // --- Top block (n=0..3): p_x = h - gb0 (frac), p_y = w+n (int)
        u = (float)h - gb[0];
        q = floorf(u);
        qlc = fminf(fmaxf(q, 0.f), 131.f);
        uc  = fminf(fmaxf(u, 0.f), 131.f);
        a[0] = 1.f + qlc - uc;
        int rT = min(max((int)qlc - 2, 0), 127);
        off[0]=rT*Wdim+cm[0]; off[1]=rT*Wdim+cm[1]; off[2]=rT*Wdim+cm[2]; off[3]=rT*Wdim+cm[3];
        // --- Right block (n=4..7): p_y = w+4+gb3 (frac), p_x = h+(n-4) (int)
        u = (float)w + 4.f + gb[3];
        q = floorf(u);
        qlc = fminf(fmaxf(q, 0.f), 131.f);
        uc  = fminf(fmaxf(u, 0.f), 131.f);
        a[1] = 1.f + qlc - uc;
        int cR = min(max((int)qlc - 2, 0), 127);
        off[4]=rm[0]*Wdim+cR; off[5]=rm[1]*Wdim+cR; off[6]=rm[2]*Wdim+cR; off[7]=rm[3]*Wdim+cR;
        // --- Bottom block (n=8..11): p_x = h+4+gb1 (frac), p_y = w+(n-7) (int; clips at 131)
        u = (float)h + 4.f + gb[1];
        q = floorf(u);
        qlc = fminf(fmaxf(q, 0.f), 131.f);
        qrc = fminf(fmaxf(q + 1.f, 0.f), 131.f);
        uc  = fminf(fmaxf(u, 0.f), 131.f);
        a[2] = 1.f + qlc - uc;
        float aBr = 1.f - (qrc - uc);
        int rB  = min(max((int)qlc - 2, 0), 127);
        int rBr = min(max((int)qrc - 2, 0), 127);
        off[8]=rB*Wdim+cm[1]; off[9]=rB*Wdim+cm[2]; off[10]=rB*Wdim+cm[3]; off[11]=rB*Wdim+cm[4];
        eBw  = (w == 127) ? aBr : 0.f;
        eBoff = rBr*Wdim + 127;
        // --- Left block (n=12..15): p_y = w - gb2 (frac), p_x = h+(n-11) (int; clips at 131)
        u = (float)w - gb[2];
        q = floorf(u);
        qlc = fminf(fmaxf(q, 0.f), 131.f);
        qrc = fminf(fmaxf(q + 1.f, 0.f), 131.f);
        uc  = fminf(fmaxf(u, 0.f), 131.f);
        a[3] = 1.f + qlc - uc;
        float aLr = 1.f - (qrc - uc);
        int cL  = min(max((int)qlc - 2, 0), 127);
        int cLr = min(max((int)qrc - 2, 0), 127);
        off[12]=rm[1]*Wdim+cL; off[13]=rm[2]*Wdim+cL; off[14]=rm[3]*Wdim+cL; off[15]=rm[4]*Wdim+cL;
        eLw  = (h == 127) ? aLr : 0.f;
        eLoff = 127*Wdim + cLr;
    }

    unsigned long long acc2[32];
    #pragma unroll
    for (int o = 0; o < 32; ++o) acc2[o] = 0ull;

    const float* Xb = x + (size_t)b*Cdim*HW;
    int ctr = h*Wdim + w;

    #pragma unroll 1
    for (int c = 0; c < Cdim; ++c) {
        const float* Xc = Xb + c*HW;
        float xc = Xc[ctr];
        float d[16];
        #pragma unroll
        for (int n = 0; n < 16; ++n)
            d[n] = fmaf(-a[n>>2], Xc[off[n]], xc);
        d[11] = fmaf(-eBw, Xc[eBoff], d[11]);
        d[15] = fmaf(-eLw, Xc[eLoff], d[15]);

        unsigned long long dp[8];
        #pragma unroll
        for (int j = 0; j < 8; ++j) dp[j] = pk2(d[2*j], d[2*j+1]);

        const ulonglong2* wc = (const ulonglong2*)(sw + c*16);   // 64B-aligned
        #pragma unroll
        for (int o = 0; o < 32; ++o) {
            const ulonglong2* wp = wc + o*128;   // o*512 floats
            ulonglong2 q0 = wp[0], q1 = wp[1], q2 = wp[2], q3 = wp[3];
            ffma2(acc2[o], q0.x, dp[0]); ffma2(acc2[o], q0.y, dp[1]);
            ffma2(acc2[o], q1.x, dp[2]); ffma2(acc2[o], q1.y, dp[3]);
            ffma2(acc2[o], q2.x, dp[4]); ffma2(acc2[o], q2.y, dp[5]);
            ffma2(acc2[o], q3.x, dp[6]); ffma2(acc2[o], q3.y, dp[7]);
        }
    }

    int obase = (b*OUTdim)*HW + ctr;
    #pragma unroll
    for (int o = 0; o < 32; ++o) {
        float lo, hi;
        unpk2(acc2[o], lo, hi);
        out[obase + o*HW] = lo + hi + sb[o];
    }
}

// =====================================================================
extern "C" void kernel_launch(void* const* d_in, const int* in_sizes, int n_in,
                              void* d_out, int out_size)
{
    const float* x      = (const float*)d_in[0];
    const float* w_vrt  = (const float*)d_in[1];
    const float* b_vrt  = (const float*)d_in[2];
    const float* g_vrt  = (const float*)d_in[3];
    const float* be_vrt = (const float*)d_in[4];
    const float* w_hrz  = (const float*)d_in[5];
    const float* b_hrz  = (const float*)d_in[6];
    const float* g_hrz  = (const float*)d_in[7];
    const float* be_hrz = (const float*)d_in[8];
    const float* w_pk   = (const float*)d_in[9];
    const float* b_pk   = (const float*)d_in[10];
    float* out = (float*)d_out;

    convbn_kernel<<<NBLK_A, 256>>>(x, w_vrt, b_vrt, w_hrz, b_hrz);
    stats_kernel<<<1, 32>>>(g_vrt, be_vrt, g_hrz, be_hrz);

    const int smem = (16384 + 32) * sizeof(float);
    cudaFuncSetAttribute(main_kernel, cudaFuncAttributeMaxDynamicSharedMemorySize, smem);
    main_kernel<<<NPIX/256, 256, smem>>>(x, w_pk, b_pk, out);
}

// round 3
// speedup vs baseline: 1.0186x; 1.0186x over previous
#include <cuda_runtime.h>
#include <math.h>

#define Bdim 8
#define Cdim 32
#define Hdim 128
#define Wdim 128
#define OUTdim 32
#define HW (Hdim*Wdim)            /* 16384 */
#define NPIX (Bdim*HW)            /* 131072 */
#define NBLK_A 512

// ---- scratch (static device globals; no runtime allocation) ----
__device__ float g_conv[4*NPIX];      // raw conv+bias outputs: v0,v1,z0,z1 planes
__device__ float g_partial[NBLK_A*8]; // per-block partial sums (4 sums + 4 sumsq)
__device__ float g_stats[12];         // mean[4], scale[4]=gamma*rsqrt(var+eps), shift[4]=beta

// ---- packed fp32x2 helpers (sm_103a FFMA2; PTX-only) ----
__device__ __forceinline__ void ffma2(unsigned long long &acc,
                                      unsigned long long w,
                                      unsigned long long d) {
    asm("fma.rn.f32x2 %0, %1, %2, %0;" : "+l"(acc) : "l"(w), "l"(d));
}
__device__ __forceinline__ unsigned long long ffma2_3(unsigned long long a,
                                                      unsigned long long b,
                                                      unsigned long long c) {
    unsigned long long r;
    asm("fma.rn.f32x2 %0, %1, %2, %3;" : "=l"(r) : "l"(a), "l"(b), "l"(c));
    return r;
}
__device__ __forceinline__ unsigned long long pk2(float lo, float hi) {
    unsigned long long r;
    asm("mov.b64 %0, {%1, %2};" : "=l"(r) : "f"(lo), "f"(hi));
    return r;
}
__device__ __forceinline__ void unpk2(unsigned long long v, float &lo, float &hi) {
    asm("mov.b64 {%0, %1}, %2;" : "=f"(lo), "=f"(hi) : "l"(v));
}

// =====================================================================
// Kernel A: 7-tap vert/horz convs (zero pad) + bias; 2 pixels/thread
// 512 blocks x 128 threads; block = 2 rows x 128 cols of one image
// =====================================================================
__global__ __launch_bounds__(128) void convbn_kernel(
    const float* __restrict__ x,
    const float* __restrict__ w_vrt, const float* __restrict__ b_vrt,
    const float* __restrict__ w_hrz, const float* __restrict__ b_hrz)
{
    __shared__ float swv[448], swh[448];   // [2][32][7]
    __shared__ float red[4][8];
    int tid = threadIdx.x;
    for (int i = tid; i < 448; i += 128) { swv[i] = w_vrt[i]; swh[i] = w_hrz[i]; }
    __syncthreads();

    int b    = blockIdx.x >> 6;            // 8 images
    int rg   = blockIdx.x & 63;            // 64 row-pairs
    int row  = rg*2 + (tid >> 6);
    int w0   = (tid & 63) * 2;
    const float* Xb = x + (size_t)b*Cdim*HW;

    float v0[2]={0,0}, v1[2]={0,0}, z0[2]={0,0}, z1[2]={0,0};

    for (int c = 0; c < Cdim; ++c) {
        const float* Xc  = Xb + c*HW;
        const float* rp  = Xc + row*Wdim;

        // vertical: 7 guarded float2 loads
        #pragma unroll
        for (int t = 0; t < 7; ++t) {
            int hh = row + t - 3;
            float2 xv = (hh >= 0 && hh < Hdim) ? *(const float2*)(Xc + hh*Wdim + w0)
                                               : make_float2(0.f, 0.f);
            float wa = swv[c*7+t], wb = swv[224 + c*7+t];
            v0[0]=fmaf(xv.x,wa,v0[0]); v0[1]=fmaf(xv.y,wa,v0[1]);
            v1[0]=fmaf(xv.x,wb,v1[0]); v1[1]=fmaf(xv.y,wb,v1[1]);
        }

        // horizontal: window w0-4 .. w0+5 as 5 guarded float2 (all-or-nothing OOB)
        float xr[10];
        #pragma unroll
        for (int l = 0; l < 5; ++l) {
            int i0 = w0 - 4 + l*2;
            float2 v = (i0 >= 0 && i0 < 127) ? *(const float2*)(rp + i0)
                                             : make_float2(0.f, 0.f);
            xr[l*2] = v.x; xr[l*2+1] = v.y;
        }
        #pragma unroll
        for (int t = 0; t < 7; ++t) {
            float wa = swh[c*7+t], wb = swh[224 + c*7+t];
            z0[0]=fmaf(xr[t+1],wa,z0[0]); z0[1]=fmaf(xr[t+2],wa,z0[1]);
            z1[0]=fmaf(xr[t+1],wb,z1[0]); z1[1]=fmaf(xr[t+2],wb,z1[1]);
        }
    }

    float bv0 = b_vrt[0], bv1 = b_vrt[1], bh0 = b_hrz[0], bh1 = b_hrz[1];
    #pragma unroll
    for (int j = 0; j < 2; ++j) { v0[j]+=bv0; v1[j]+=bv1; z0[j]+=bh0; z1[j]+=bh1; }

    int pixbase = b*HW + row*Wdim + w0;
    *(float2*)&g_conv[          pixbase] = make_float2(v0[0],v0[1]);
    *(float2*)&g_conv[  NPIX +  pixbase] = make_float2(v1[0],v1[1]);
    *(float2*)&g_conv[2*NPIX +  pixbase] = make_float2(z0[0],z0[1]);
    *(float2*)&g_conv[3*NPIX +  pixbase] = make_float2(z1[0],z1[1]);

    float vals[8];
    vals[0]=v0[0]+v0[1]; vals[1]=v1[0]+v1[1]; vals[2]=z0[0]+z0[1]; vals[3]=z1[0]+z1[1];
    vals[4]=v0[0]*v0[0]+v0[1]*v0[1]; vals[5]=v1[0]*v1[0]+v1[1]*v1[1];
    vals[6]=z0[0]*z0[0]+z0[1]*z0[1]; vals[7]=z1[0]*z1[0]+z1[1]*z1[1];

    #pragma unroll
    for (int k = 0; k < 8; ++k) {
        float s = vals[k];
        #pragma unroll
        for (int off = 16; off; off >>= 1) s += __shfl_down_sync(0xffffffffu, s, off);
        if ((tid & 31) == 0) red[tid>>5][k] = s;
    }
    __syncthreads();
    if (tid < 8) {
        float s = red[0][tid] + red[1][tid] + red[2][tid] + red[3][tid];
        g_partial[blockIdx.x*8 + tid] = s;
    }
}

// =====================================================================
// Kernel B: finalize BN stats (deterministic)
// =====================================================================
__global__ void stats_kernel(
    const float* __restrict__ g_vrt, const float* __restrict__ be_vrt,
    const float* __restrict__ g_hrz, const float* __restrict__ be_hrz)
{
    __shared__ float sh[8];
    int k = threadIdx.x;
    if (k < 8) {
        float s = 0.f;
        #pragma unroll 8
        for (int i = 0; i < NBLK_A; ++i) s += g_partial[i*8 + k];
        sh[k] = s;
    }
    __syncwarp();
    if (k < 4) {
        const float inv = 1.f / (float)NPIX;
        float mean = sh[k] * inv;
        float var  = sh[k+4] * inv - mean*mean;
        float gamma = (k < 2) ? g_vrt[k] : g_hrz[k-2];
        float beta  = (k < 2) ? be_vrt[k] : be_hrz[k-2];
        g_stats[k]     = mean;
        g_stats[4 + k] = gamma * rsqrtf(var + 1e-5f);
        g_stats[8 + k] = beta;
    }
}

// =====================================================================
// Kernel C: per-pixel deformable sampling + 32x512 matvec (f32x2 packed,
// spill-free: offsets packed 2x16-bit, sampling computed directly packed)
// =====================================================================
__global__ __launch_bounds__(256, 2) void main_kernel(
    const float* __restrict__ x, const float* __restrict__ w_pk,
    const float* __restrict__ b_pk, float* __restrict__ out)
{
    extern __shared__ float sw[];          // w_pk [32][32][16] = 16384 floats, + bias 32
    float* sb = sw + 16384;
    int tid = threadIdx.x;
    {
        const float4* src = (const float4*)w_pk;
        float4* dst = (float4*)sw;
        #pragma unroll
        for (int i = 0; i < 16; ++i) dst[tid + i*256] = src[tid + i*256];
        if (tid < 32) sb[tid] = b_pk[tid];
    }
    __syncthreads();

    int pix = blockIdx.x*256 + tid;
    int b = pix >> 14; int rem = pix & (HW-1); int h = rem >> 7; int w = rem & 127;

    // gb0..gb3 = 2*sigmoid(BN(conv))
    float gb[4];
    #pragma unroll
    for (int j = 0; j < 4; ++j) {
        float cv = g_conv[j*NPIX + pix];
        float t = (cv - g_stats[j]) * g_stats[4+j] + g_stats[8+j];
        gb[j] = 2.f / (1.f + expf(-t));
    }

    int rm[5], cm[5];
    #pragma unroll
    for (int i = 0; i < 5; ++i) {
        rm[i] = min(max(h + i - 2, 0), 127);
        cm[i] = min(max(w + i - 2, 0), 127);
    }

    unsigned int offp[8];                  // 16 gather offsets, 2x16-bit packed
    unsigned long long na2[4];             // (-a_k, -a_k) packed
    unsigned long long eB2, eL2;           // (0, -edgeWeight) packed
    int eBoff, eLoff;
    {
        int off[16];
        float u, q, qlc, qrc, uc, a;
        // --- Top block (n=0..3): p_x = h - gb0 (frac), p_y = w+n (int)
        u = (float)h - gb[0];
        q = floorf(u);
        qlc = fminf(fmaxf(q, 0.f), 131.f);
        uc  = fminf(fmaxf(u, 0.f), 131.f);
        a = 1.f + qlc - uc; na2[0] = pk2(-a, -a);
        int rT = min(max((int)qlc - 2, 0), 127);
        off[0]=rT*Wdim+cm[0]; off[1]=rT*Wdim+cm[1]; off[2]=rT*Wdim+cm[2]; off[3]=rT*Wdim+cm[3];
        // --- Right block (n=4..7): p_y = w+4+gb3 (frac), p_x = h+(n-4) (int)
        u = (float)w + 4.f + gb[3];
        q = floorf(u);
        qlc = fminf(fmaxf(q, 0.f), 131.f);
        uc  = fminf(fmaxf(u, 0.f), 131.f);
        a = 1.f + qlc - uc; na2[1] = pk2(-a, -a);
        int cR = min(max((int)qlc - 2, 0), 127);
        off[4]=rm[0]*Wdim+cR; off[5]=rm[1]*Wdim+cR; off[6]=rm[2]*Wdim+cR; off[7]=rm[3]*Wdim+cR;
        // --- Bottom block (n=8..11): p_x = h+4+gb1 (frac), p_y = w+(n-7) (int; clips at 131)
        u = (float)h + 4.f + gb[1];
        q = floorf(u);
        qlc = fminf(fmaxf(q, 0.f), 131.f);
        qrc = fminf(fmaxf(q + 1.f, 0.f), 131.f);
        uc  = fminf(fmaxf(u, 0.f), 131.f);
        a = 1.f + qlc - uc; na2[2] = pk2(-a, -a);
        float aBr = 1.f - (qrc - uc);
        int rB  = min(max((int)qlc - 2, 0), 127);
        int rBr = min(max((int)qrc - 2, 0), 127);
        off[8]=rB*Wdim+cm[1]; off[9]=rB*Wdim+cm[2]; off[10]=rB*Wdim+cm[3]; off[11]=rB*Wdim+cm[4];
        float eBw = (w == 127) ? aBr : 0.f;   // rb corner live only at p_y clip (n=11,w=127)
        eB2 = pk2(0.f, -eBw);
        eBoff = rBr*Wdim + 127;
        // --- Left block (n=12..15): p_y = w - gb2 (frac), p_x = h+(n-11) (int; clips at 131)
        u = (float)w - gb[2];
        q = floorf(u);
        qlc = fminf(fmaxf(q, 0.f), 131.f);
        qrc = fminf(fmaxf(q + 1.f, 0.f), 131.f);
        uc  = fminf(fmaxf(u, 0.f), 131.f);
        a = 1.f + qlc - uc; na2[3] = pk2(-a, -a);
        float aLr = 1.f - (qrc - uc);
        int cL  = min(max((int)qlc - 2, 0), 127);
        int cLr = min(max((int)qrc - 2, 0), 127);
        off[12]=rm[1]*Wdim+cL; off[13]=rm[2]*Wdim+cL; off[14]=rm[3]*Wdim+cL; off[15]=rm[4]*Wdim+cL;
        float eLw = (h == 127) ? aLr : 0.f;   // rb corner live only at p_x clip (n=15,h=127)
        eL2 = pk2(0.f, -eLw);
        eLoff = 127*Wdim + cLr;

        #pragma unroll
        for (int j = 0; j < 8; ++j)
            offp[j] = (unsigned int)off[2*j] | ((unsigned int)off[2*j+1] << 16);
    }

    unsigned long long acc2[32];
    #pragma unroll
    for (int o = 0; o < 32; ++o) acc2[o] = 0ull;

    const float* Xb = x + (size_t)b*Cdim*HW;
    int ctr = h*Wdim + w;

    #pragma unroll 1
    for (int c = 0; c < Cdim; ++c) {
        const float* Xc = Xb + c*HW;
        float xc = Xc[ctr];
        unsigned long long xc2 = pk2(xc, xc);

        unsigned long long dp[8];
        #pragma unroll
        for (int j = 0; j < 8; ++j) {
            int o0 = (int)(offp[j] & 0xFFFFu);
            int o1 = (int)(offp[j] >> 16);
            unsigned long long xp = pk2(Xc[o0], Xc[o1]);
            dp[j] = ffma2_3(na2[j>>1], xp, xc2);      // (xc - a*X0, xc - a*X1)
        }
        {   // edge corner fixups (hi lanes of pairs 5 and 7)
            float xe = Xc[eBoff];
            ffma2(dp[5], eB2, pk2(xe, xe));
            float xl = Xc[eLoff];
            ffma2(dp[7], eL2, pk2(xl, xl));
        }

        const ulonglong2* wc = (const ulonglong2*)(sw + c*16);   // 64B-aligned
        #pragma unroll
        for (int o = 0; o < 32; ++o) {
            const ulonglong2* wp = wc + o*128;   // o*512 floats
            ulonglong2 q0 = wp[0], q1 = wp[1], q2 = wp[2], q3 = wp[3];
            ffma2(acc2[o], q0.x, dp[0]); ffma2(acc2[o], q0.y, dp[1]);
            ffma2(acc2[o], q1.x, dp[2]); ffma2(acc2[o], q1.y, dp[3]);
            ffma2(acc2[o], q2.x, dp[4]); ffma2(acc2[o], q2.y, dp[5]);
            ffma2(acc2[o], q3.x, dp[6]); ffma2(acc2[o], q3.y, dp[7]);
        }
    }

    int obase = (b*OUTdim)*HW + ctr;
    #pragma unroll
    for (int o = 0; o < 32; ++o) {
        float lo, hi;
        unpk2(acc2[o], lo, hi);
        out[obase + o*HW] = lo + hi + sb[o];
    }
}

// =====================================================================
extern "C" void kernel_launch(void* const* d_in, const int* in_sizes, int n_in,
                              void* d_out, int out_size)
{
    const float* x      = (const float*)d_in[0];
    const float* w_vrt  = (const float*)d_in[1];
    const float* b_vrt  = (const float*)d_in[2];
    const float* g_vrt  = (const float*)d_in[3];
    const float* be_vrt = (const float*)d_in[4];
    const float* w_hrz  = (const float*)d_in[5];
    const float* b_hrz  = (const float*)d_in[6];
    const float* g_hrz  = (const float*)d_in[7];
    const float* be_hrz = (const float*)d_in[8];
    const float* w_pk   = (const float*)d_in[9];
    const float* b_pk   = (const float*)d_in[10];
    float* out = (float*)d_out;

    convbn_kernel<<<NBLK_A, 128>>>(x, w_vrt, b_vrt, w_hrz, b_hrz);
    stats_kernel<<<1, 32>>>(g_vrt, be_vrt, g_hrz, be_hrz);

    const int smem = (16384 + 32) * sizeof(float);
    cudaFuncSetAttribute(main_kernel, cudaFuncAttributeMaxDynamicSharedMemorySize, smem);
    main_kernel<<<NPIX/256, 256, smem>>>(x, w_pk, b_pk, out);
}